// round 9
// baseline (speedup 1.0000x reference)
#include <cuda_runtime.h>
#include <cuda_fp16.h>
#include <cstdint>
#include <float.h>

// Problem constants (fixed shapes from reference setup_inputs)
constexpr int NQ   = 16384;
constexpr int NC   = 8192;
constexpr int CDIM = 256;
constexpr int TM   = 64;        // queries per block (pass 1)
constexpr int TN   = 256;       // codes per n-tile (A-frag reuse across 256)
constexpr int KT   = 64;        // k-halves per E chunk
constexpr int QST  = 264;       // Q smem row stride (halves)
constexpr int EST  = 72;        // E chunk smem row stride (halves)
constexpr int NTILES = NC / TN;        // 32
constexpr int NCHUNK = NTILES * 4;     // 128 chunks

// Rescue margin: single-pass fp16 distance error sd ~1.4e-4 (dominated by
// e_hi quantization). DELTA = 2.5e-3 is ~18 sigma. Flagged -> exact rescore.
constexpr float DELTA = 2.5e-3f;

// SMEM byte offsets (pass 1)
constexpr int OFF_QH  = 0;                  // 64*264*2  = 33792
constexpr int OFF_EH  = 33792;              // 2 bufs * 256*72*2 = 73728
constexpr int OFF_ESQ = 107520;             // 256 floats
constexpr int OFF_QSQ = 108544;             // 64 floats
constexpr int SMEM_TOTAL = 108800;

__device__ __half g_QH[NQ * CDIM];
__device__ __half g_EH[NC * CDIM];
__device__ float  g_esq[NC];
__device__ float  g_qsq[NQ];
__device__ float  g_dist_sum;
__device__ int    g_prov[NQ];                  // provisional winner (pass 1)
__device__ unsigned long long g_key[NQ];       // rescored (dist,idx) key
__device__ int    g_flist[NQ];                 // flagged query list
__device__ int    g_nflag;

// ---------------------------------------------------------------------------
// Compensated fp32 two-sum
// ---------------------------------------------------------------------------
__device__ __forceinline__ void two_sum(float a, float b, float& s, float& e) {
    s = a + b;
    float bp = s - a;
    e = (a - (s - bp)) + (b - bp);
}

// ---------------------------------------------------------------------------
// Fused prep: accumulator init + fp16 convert (exact pow2 pre-scale) +
// compensated sumsq. One warp per 256-float row.
// ---------------------------------------------------------------------------
__global__ void vq_prep_kernel(const float* __restrict__ Q,
                               const float* __restrict__ E) {
    if (blockIdx.x == 0 && threadIdx.x == 0) {
        g_dist_sum = 0.0f;
        g_nflag = 0;
    }
    const int gwarp = (blockIdx.x * blockDim.x + threadIdx.x) >> 5;
    const int lane  = threadIdx.x & 31;
    if (gwarp >= NC + NQ) return;

    const bool isE = (gwarp < NC);
    const float* src = isE ? (E + (size_t)gwarp * CDIM)
                           : (Q + (size_t)(gwarp - NC) * CDIM);
    const float scale = isE ? 64.0f : 16.0f;
    __half* dst = isE ? (g_EH + (size_t)gwarp * CDIM)
                      : (g_QH + (size_t)(gwarp - NC) * CDIM);

    float4 a = reinterpret_cast<const float4*>(src)[lane];
    float4 b = reinterpret_cast<const float4*>(src)[lane + 32];

    // fp16 convert (scaled); 8 halves -> two 8B stores
    {
        __half2 h[4];
        h[0] = __floats2half2_rn(a.x * scale, a.y * scale);
        h[1] = __floats2half2_rn(a.z * scale, a.w * scale);
        h[2] = __floats2half2_rn(b.x * scale, b.y * scale);
        h[3] = __floats2half2_rn(b.z * scale, b.w * scale);
        const uint2* p = reinterpret_cast<const uint2*>(h);
        *reinterpret_cast<uint2*>(dst + lane * 4)       = p[0];
        *reinterpret_cast<uint2*>(dst + 128 + lane * 4) = p[1];
    }

    // compensated sumsq of the ORIGINAL values
    float v[8] = {a.x, a.y, a.z, a.w, b.x, b.y, b.z, b.w};
    float s = 0.0f, c = 0.0f;
    #pragma unroll
    for (int k = 0; k < 8; ++k) {
        float p = v[k] * v[k];
        float r = __fmaf_rn(v[k], v[k], -p);
        float t, e;
        two_sum(s, p, t, e);
        s = t; c += e + r;
    }
    #pragma unroll
    for (int off = 16; off; off >>= 1) {
        float so = __shfl_down_sync(0xffffffffu, s, off);
        float co = __shfl_down_sync(0xffffffffu, c, off);
        float t, e;
        two_sum(s, so, t, e);
        s = t; c += e + co;
    }
    if (lane == 0) {
        float total = s + c;
        if (isE) g_esq[gwarp]      = total;
        else     g_qsq[gwarp - NC] = total;
    }
}

// ---------------------------------------------------------------------------
// PTX helpers
// ---------------------------------------------------------------------------
__device__ __forceinline__ uint32_t smem_u32(const void* p) {
    return (uint32_t)__cvta_generic_to_shared(p);
}
__device__ __forceinline__ void ldsm4(uint32_t& r0, uint32_t& r1,
                                      uint32_t& r2, uint32_t& r3, uint32_t a) {
    asm volatile("ldmatrix.sync.aligned.m8n8.x4.shared.b16 {%0,%1,%2,%3},[%4];"
                 : "=r"(r0), "=r"(r1), "=r"(r2), "=r"(r3) : "r"(a));
}
__device__ __forceinline__ void mma16816(float* c,
                                         uint32_t a0, uint32_t a1,
                                         uint32_t a2, uint32_t a3,
                                         uint32_t b0, uint32_t b1) {
    asm("mma.sync.aligned.m16n8k16.row.col.f32.f16.f16.f32 "
        "{%0,%1,%2,%3},{%4,%5,%6,%7},{%8,%9},{%0,%1,%2,%3};"
        : "+f"(c[0]), "+f"(c[1]), "+f"(c[2]), "+f"(c[3])
        : "r"(a0), "r"(a1), "r"(a2), "r"(a3), "r"(b0), "r"(b1));
}
__device__ __forceinline__ void cp_async16(uint32_t s, const void* g) {
    asm volatile("cp.async.cg.shared.global [%0],[%1],16;" :: "r"(s), "l"(g));
}
__device__ __forceinline__ void cp_commit() {
    asm volatile("cp.async.commit_group;");
}
__device__ __forceinline__ void cp_wait0() {
    asm volatile("cp.async.wait_group 0;" ::: "memory");
}

// ---------------------------------------------------------------------------
// Pass 1: single-pass fp16 tensor-core distance GEMM + top-2 + flagging.
// dist = fl( fl(qsq+esq) - 2^-9 * acc ). Block: 256 thr, 8 warps as
// 2 M-warps x 4 N-warps; warp tile 32 rows x 64 cols; TM=64, TN=256.
// ---------------------------------------------------------------------------
__global__ void __launch_bounds__(256, 2)
vq_main_kernel() {
    extern __shared__ char smem[];
    __half* QHs   = (__half*)(smem + OFF_QH);
    __half* EHs   = (__half*)(smem + OFF_EH);
    float*  esq_s = (float*)(smem + OFF_ESQ);
    float*  qsq_s = (float*)(smem + OFF_QSQ);
    // overlay (used only after the main loop, behind a barrier)
    float*  redMin  = (float*)(smem + OFF_EH);
    int*    redIdx  = (int*)  (smem + OFF_EH + 4096);
    float*  redMin2 = (float*)(smem + OFF_EH + 8192);

    const int tid  = threadIdx.x;
    const int lane = tid & 31;
    const int warp = tid >> 5;
    const int wm = warp >> 2;        // 0..1 (M warps, 32 rows each)
    const int wn = warp & 3;         // 0..3 (N warps, 64 cols each)
    const int qbase = blockIdx.x * TM;

    // ---- Prologue: Q tile + E chunk 0 in one cp.async group ----
    {
        const __half* gQH = g_QH + (size_t)qbase * CDIM;
        #pragma unroll
        for (int t = 0; t < 8; ++t) {
            int s = tid + t * 256;              // 2048 16B-segs
            int row = s >> 5, col = (s & 31) << 3;
            cp_async16(smem_u32(QHs + row * QST + col), gQH + row * CDIM + col);
        }
        #pragma unroll
        for (int t = 0; t < 8; ++t) {           // chunk 0: 256 rows x 128B
            int s = tid + t * 256;
            int row = s >> 3, col = (s & 7) << 3;
            cp_async16(smem_u32(EHs + row * EST + col), g_EH + row * CDIM + col);
        }
        cp_commit();
    }
    if (tid < TM) qsq_s[tid] = g_qsq[qbase + tid];

    float acc[2][8][4];
    float runMin[4], runMin2[4];
    int   runIdx[4];
    float qsq_r[4];
    #pragma unroll
    for (int r = 0; r < 4; ++r) {
        runMin[r] = FLT_MAX; runMin2[r] = FLT_MAX; runIdx[r] = 0;
    }

    const int a_row  = wm * 32 + (lane & 15);
    const int a_colb = (lane >> 4) << 3;
    const int b_n    = wn * 64 + (lane & 7) + ((lane >> 4) << 3);
    const int b_k    = ((lane >> 3) & 1) << 3;
    const int tl = lane & 3, gid = lane >> 2;

    for (int cc = 0; cc < NCHUNK; ++cc) {
        const int nt = cc >> 2, kt = cc & 3;
        cp_wait0();                // chunk cc resident
        __syncthreads();           // everyone done with buf (cc-1)&1
        if (cc == 0) {
            #pragma unroll
            for (int r = 0; r < 4; ++r)
                qsq_r[r] = qsq_s[wm * 32 + (r >> 1) * 16 + gid + (r & 1) * 8];
        }
        // prefetch next chunk into the other buffer
        if (cc + 1 < NCHUNK) {
            int nn = (cc + 1) >> 2, nk = (cc + 1) & 3;
            const __half* gEH = g_EH + (size_t)(nn * TN) * CDIM + nk * KT;
            __half* dEH = EHs + ((cc + 1) & 1) * (TN * EST);
            #pragma unroll
            for (int t = 0; t < 8; ++t) {
                int s = tid + t * 256;
                int row = s >> 3, col = (s & 7) << 3;
                cp_async16(smem_u32(dEH + row * EST + col), gEH + row * CDIM + col);
            }
            cp_commit();
        }
        if (kt == 0) {
            esq_s[tid] = g_esq[nt * TN + tid];   // 256 threads, 256 cols
            #pragma unroll
            for (int i = 0; i < 2; ++i) {
                #pragma unroll
                for (int j = 0; j < 8; ++j) {
                    #pragma unroll
                    for (int c2 = 0; c2 < 4; ++c2) acc[i][j][c2] = 0.0f;
                }
            }
        }

        // ---- compute chunk: 4 k16-steps; per ks: 6 ldsm.x4 + 16 HMMA ----
        const __half* bEH = EHs + (cc & 1) * (TN * EST);
        #pragma unroll
        for (int ks = 0; ks < 4; ++ks) {
            uint32_t ah[2][4];
            #pragma unroll
            for (int i = 0; i < 2; ++i) {
                int col = kt * KT + ks * 16 + a_colb;
                ldsm4(ah[i][0], ah[i][1], ah[i][2], ah[i][3],
                      smem_u32(QHs + (a_row + i * 16) * QST + col));
            }
            #pragma unroll
            for (int jj = 0; jj < 4; ++jj) {
                uint32_t bh[4];
                int ecol = ks * 16 + b_k;
                ldsm4(bh[0], bh[1], bh[2], bh[3],
                      smem_u32(bEH + (b_n + jj * 16) * EST + ecol));
                #pragma unroll
                for (int i = 0; i < 2; ++i) {
                    mma16816(acc[i][jj*2+0], ah[i][0],ah[i][1],ah[i][2],ah[i][3], bh[0],bh[1]);
                    mma16816(acc[i][jj*2+1], ah[i][0],ah[i][1],ah[i][2],ah[i][3], bh[2],bh[3]);
                }
            }
        }

        if (kt == 3) {
            // Epilogue: ascending n within lane; strict '<' = first index.
            // -2^-9 folds the 1/1024 (=16*64) de-scale with the -2 factor.
            #pragma unroll
            for (int j = 0; j < 8; ++j) {
                int nloc = wn * 64 + j * 8 + tl * 2;
                float2 es = *(const float2*)(esq_s + nloc);
                int n0 = nt * TN + nloc;
                #pragma unroll
                for (int i = 0; i < 2; ++i) {
                    #pragma unroll
                    for (int h = 0; h < 2; ++h) {
                        int r = i * 2 + h;
                        float t0 = __fadd_rn(qsq_r[r], es.x);
                        float d  = __fmaf_rn(-0.001953125f, acc[i][j][h*2+0], t0);
                        if (d < runMin[r]) {
                            runMin2[r] = runMin[r];
                            runMin[r] = d; runIdx[r] = n0;
                        } else if (d < runMin2[r]) runMin2[r] = d;
                        t0 = __fadd_rn(qsq_r[r], es.y);
                        d  = __fmaf_rn(-0.001953125f, acc[i][j][h*2+1], t0);
                        if (d < runMin[r]) {
                            runMin2[r] = runMin[r];
                            runMin[r] = d; runIdx[r] = n0 + 1;
                        } else if (d < runMin2[r]) runMin2[r] = d;
                    }
                }
            }
        }
    }

    // ---- Cross-lane top-2 reduction: [64 rows][16 slots] ----
    __syncthreads();   // all compute + async copies done; safe to overlay
    {
        const int slot = wn * 4 + tl;
        #pragma unroll
        for (int r = 0; r < 4; ++r) {
            int m = wm * 32 + (r >> 1) * 16 + gid + (r & 1) * 8;
            redMin [m * 16 + slot] = runMin[r];
            redIdx [m * 16 + slot] = runIdx[r];
            redMin2[m * 16 + slot] = runMin2[r];
        }
    }
    __syncthreads();

    float myDist = 0.0f;
    if (tid < TM) {
        float m1 = FLT_MAX, m2 = FLT_MAX; int i1 = 0;
        #pragma unroll
        for (int s2 = 0; s2 < 16; ++s2) {
            float v1 = redMin [tid * 16 + s2];
            int   id = redIdx [tid * 16 + s2];
            float v2 = redMin2[tid * 16 + s2];
            if (v1 < m1 || (v1 == m1 && id < i1)) {
                m2 = (m1 < m2) ? m1 : m2;
                m1 = v1; i1 = id;
            } else {
                m2 = (v1 < m2) ? v1 : m2;
            }
            m2 = (v2 < m2) ? v2 : m2;
        }
        int q = qbase + tid;
        g_key[q]  = ~0ull;
        g_prov[q] = i1;
        if (m2 - m1 <= DELTA) {
            int slot = atomicAdd(&g_nflag, 1);
            g_flist[slot] = q;
        }
        myDist = m1;
    }
    #pragma unroll
    for (int off = 16; off; off >>= 1)
        myDist += __shfl_down_sync(0xffffffffu, myDist, off);
    if (lane == 0 && warp < 2) atomicAdd(&g_dist_sum, myDist);
}

// ---------------------------------------------------------------------------
// Pass 2: exact rescore of flagged queries over ALL codes — arithmetic
// bit-identical to the verified Round-2 kernel (ascending-k fp32 FMA chain).
// First-index ties via atomicMin on (dist_bits<<32 | idx); dist > 0.
// ---------------------------------------------------------------------------
constexpr int G2 = 2048;

__global__ void __launch_bounds__(128)
vq_rescore_kernel(const float* __restrict__ Q, const float* __restrict__ E) {
    __shared__ float Qrow[CDIM];
    __shared__ float qsq_sh;
    const int nf = g_nflag;
    for (int w = blockIdx.x; w < nf * 32; w += G2) {
        const int q  = g_flist[w >> 5];
        const int n0 = (w & 31) * 256;
        __syncthreads();    // previous iteration done with Qrow
        for (int t = threadIdx.x; t < CDIM; t += 128)
            Qrow[t] = Q[(size_t)q * CDIM + t];
        if (threadIdx.x == 0) qsq_sh = g_qsq[q];
        __syncthreads();
        #pragma unroll
        for (int c = 0; c < 2; ++c) {
            int n = n0 + threadIdx.x + c * 128;
            const float4* e4 = reinterpret_cast<const float4*>(
                E + (size_t)n * CDIM);
            float acc = 0.0f;
            #pragma unroll 8
            for (int k4 = 0; k4 < 64; ++k4) {
                float4 ev = e4[k4];
                acc = __fmaf_rn(Qrow[k4*4+0], ev.x, acc);
                acc = __fmaf_rn(Qrow[k4*4+1], ev.y, acc);
                acc = __fmaf_rn(Qrow[k4*4+2], ev.z, acc);
                acc = __fmaf_rn(Qrow[k4*4+3], ev.w, acc);
            }
            float t0 = __fadd_rn(qsq_sh, g_esq[n]);
            float d  = __fmaf_rn(-2.0f, acc, t0);   // d > 0 always here
            unsigned long long key =
                ((unsigned long long)__float_as_uint(d) << 32) | (unsigned)n;
            atomicMin(&g_key[q], key);
        }
    }
}

// ---------------------------------------------------------------------------
// Pass 3: finalize indices + gather quantized rows + loss scalar.
// One warp per query.
// ---------------------------------------------------------------------------
__global__ void __launch_bounds__(256)
vq_final3_kernel(const float* __restrict__ E, float* __restrict__ out,
                 float* __restrict__ out_loss) {
    if (blockIdx.x == 0 && threadIdx.x == 0)
        *out_loss = 1.25f * g_dist_sum * (1.0f / ((float)NQ * (float)CDIM));
    const int q    = blockIdx.x * 8 + (threadIdx.x >> 5);
    const int lane = threadIdx.x & 31;
    unsigned long long k = g_key[q];
    int idx = (k != ~0ull) ? (int)(k & 0xffffffffu) : g_prov[q];
    if (lane == 0) out[q] = (float)idx;
    const float4* src = reinterpret_cast<const float4*>(E + (size_t)idx * CDIM);
    float4* dst = reinterpret_cast<float4*>(out + NQ + (size_t)q * CDIM);
    dst[lane]      = src[lane];
    dst[lane + 32] = src[lane + 32];
}

extern "C" void kernel_launch(void* const* d_in, const int* in_sizes, int n_in,
                              void* d_out, int out_size) {
    const float* Q = (const float*)d_in[0];
    const float* E = (const float*)d_in[1];
    float* out = (float*)d_out;

    cudaFuncSetAttribute(vq_main_kernel,
                         cudaFuncAttributeMaxDynamicSharedMemorySize,
                         SMEM_TOTAL);

    vq_prep_kernel<<<(NC + NQ) / 8, 256>>>(Q, E);
    vq_main_kernel<<<NQ / TM, 256, SMEM_TOTAL>>>();
    vq_rescore_kernel<<<G2, 128>>>(Q, E);
    vq_final3_kernel<<<NQ / 8, 256>>>(E, out, out + out_size - 1);
}

// round 10
// speedup vs baseline: 1.7942x; 1.7942x over previous
#include <cuda_runtime.h>
#include <cuda_fp16.h>
#include <cstdint>
#include <float.h>

// Problem constants (fixed shapes from reference setup_inputs)
constexpr int NQ   = 16384;
constexpr int NC   = 8192;
constexpr int CDIM = 256;
constexpr int TM   = 64;        // queries per block (pass 1)
constexpr int TN   = 128;       // codes per n-tile
constexpr int KT   = 64;        // k-halves per E chunk
constexpr int QST  = 264;       // Q smem row stride (halves)
constexpr int EST  = 72;        // E chunk smem row stride (halves)
constexpr int NTILES = NC / TN;        // 64
constexpr int NCHUNK = NTILES * 4;     // 256 chunks

// Rescue margin: single-pass fp16 distance error sd ~1.8e-4 -> 2e-3 ~ 8 sigma.
constexpr float DELTA = 2.0e-3f;

// SMEM byte offsets (pass-1 main kernel)
constexpr int OFF_QH  = 0;                  // 64*264*2  = 33792
constexpr int OFF_EH  = 33792;              // 2 bufs * 128*72*2 = 36864
constexpr int OFF_ESQ = 70656;              // 128 floats
constexpr int OFF_QSQ = 71168;              // 64 floats
constexpr int SMEM_TOTAL = 71424;

// Rescore kernel geometry
constexpr int RC     = 128;                 // codes per rescore block
constexpr int RES_ST = 260;                 // padded fp32 row stride (floats)
constexpr int RSMEM  = (RC * RES_ST + 4 * CDIM + 8 + RC) * 4;  // ~137 KB

__device__ __half g_QH[NQ * CDIM];
__device__ __half g_EH[NC * CDIM];
__device__ float  g_esq[NC];
__device__ float  g_qsq[NQ];
__device__ float  g_dist_sum;
__device__ int    g_prov[NQ];                  // provisional winner (pass 1)
__device__ unsigned long long g_key[NQ];       // rescored (dist,idx) key
__device__ int    g_flist[NQ];                 // flagged query list
__device__ int    g_nflag;

// ---------------------------------------------------------------------------
__device__ __forceinline__ void two_sum(float a, float b, float& s, float& e) {
    s = a + b;
    float bp = s - a;
    e = (a - (s - bp)) + (b - bp);
}

// ---------------------------------------------------------------------------
// Fused prep: init + fp16 convert (exact pow2 pre-scale) + compensated sumsq.
// One warp per 256-float row.
// ---------------------------------------------------------------------------
__global__ void vq_prep_kernel(const float* __restrict__ Q,
                               const float* __restrict__ E) {
    if (blockIdx.x == 0 && threadIdx.x == 0) {
        g_dist_sum = 0.0f;
        g_nflag = 0;
    }
    const int gwarp = (blockIdx.x * blockDim.x + threadIdx.x) >> 5;
    const int lane  = threadIdx.x & 31;
    if (gwarp >= NC + NQ) return;

    const bool isE = (gwarp < NC);
    const float* src = isE ? (E + (size_t)gwarp * CDIM)
                           : (Q + (size_t)(gwarp - NC) * CDIM);
    const float scale = isE ? 64.0f : 16.0f;
    __half* dst = isE ? (g_EH + (size_t)gwarp * CDIM)
                      : (g_QH + (size_t)(gwarp - NC) * CDIM);

    float4 a = reinterpret_cast<const float4*>(src)[lane];
    float4 b = reinterpret_cast<const float4*>(src)[lane + 32];

    {
        __half2 h[4];
        h[0] = __floats2half2_rn(a.x * scale, a.y * scale);
        h[1] = __floats2half2_rn(a.z * scale, a.w * scale);
        h[2] = __floats2half2_rn(b.x * scale, b.y * scale);
        h[3] = __floats2half2_rn(b.z * scale, b.w * scale);
        const uint2* p = reinterpret_cast<const uint2*>(h);
        *reinterpret_cast<uint2*>(dst + lane * 4)       = p[0];
        *reinterpret_cast<uint2*>(dst + 128 + lane * 4) = p[1];
    }

    float v[8] = {a.x, a.y, a.z, a.w, b.x, b.y, b.z, b.w};
    float s = 0.0f, c = 0.0f;
    #pragma unroll
    for (int k = 0; k < 8; ++k) {
        float p = v[k] * v[k];
        float r = __fmaf_rn(v[k], v[k], -p);
        float t, e;
        two_sum(s, p, t, e);
        s = t; c += e + r;
    }
    #pragma unroll
    for (int off = 16; off; off >>= 1) {
        float so = __shfl_down_sync(0xffffffffu, s, off);
        float co = __shfl_down_sync(0xffffffffu, c, off);
        float t, e;
        two_sum(s, so, t, e);
        s = t; c += e + co;
    }
    if (lane == 0) {
        float total = s + c;
        if (isE) g_esq[gwarp]      = total;
        else     g_qsq[gwarp - NC] = total;
    }
}

// ---------------------------------------------------------------------------
// PTX helpers
// ---------------------------------------------------------------------------
__device__ __forceinline__ uint32_t smem_u32(const void* p) {
    return (uint32_t)__cvta_generic_to_shared(p);
}
__device__ __forceinline__ void ldsm4(uint32_t& r0, uint32_t& r1,
                                      uint32_t& r2, uint32_t& r3, uint32_t a) {
    asm volatile("ldmatrix.sync.aligned.m8n8.x4.shared.b16 {%0,%1,%2,%3},[%4];"
                 : "=r"(r0), "=r"(r1), "=r"(r2), "=r"(r3) : "r"(a));
}
__device__ __forceinline__ void mma16816(float* c,
                                         uint32_t a0, uint32_t a1,
                                         uint32_t a2, uint32_t a3,
                                         uint32_t b0, uint32_t b1) {
    asm("mma.sync.aligned.m16n8k16.row.col.f32.f16.f16.f32 "
        "{%0,%1,%2,%3},{%4,%5,%6,%7},{%8,%9},{%0,%1,%2,%3};"
        : "+f"(c[0]), "+f"(c[1]), "+f"(c[2]), "+f"(c[3])
        : "r"(a0), "r"(a1), "r"(a2), "r"(a3), "r"(b0), "r"(b1));
}
__device__ __forceinline__ void cp_async16(uint32_t s, const void* g) {
    asm volatile("cp.async.cg.shared.global [%0],[%1],16;" :: "r"(s), "l"(g));
}
__device__ __forceinline__ void cp_commit() {
    asm volatile("cp.async.commit_group;");
}
__device__ __forceinline__ void cp_wait0() {
    asm volatile("cp.async.wait_group 0;" ::: "memory");
}

// ---------------------------------------------------------------------------
// Pass 1: single-pass fp16 tensor-core distance GEMM + top-2 + flagging.
// dist = fl( fl(qsq+esq) - 2^-9 * acc ). 8 warps: 2 M x 4 N; warp tile 32x32.
// (R7-verified skeleton with the lo-pass removed; acc = 32 regs, no spills.)
// ---------------------------------------------------------------------------
__global__ void __launch_bounds__(256, 2)
vq_main_kernel() {
    extern __shared__ char smem[];
    __half* QHs   = (__half*)(smem + OFF_QH);
    __half* EHs   = (__half*)(smem + OFF_EH);
    float*  esq_s = (float*)(smem + OFF_ESQ);
    float*  qsq_s = (float*)(smem + OFF_QSQ);
    // overlay (used only after the main loop, behind a barrier)
    float*  redMin  = (float*)(smem + OFF_EH);
    int*    redIdx  = (int*)  (smem + OFF_EH + 4096);
    float*  redMin2 = (float*)(smem + OFF_EH + 8192);

    const int tid  = threadIdx.x;
    const int lane = tid & 31;
    const int warp = tid >> 5;
    const int wm = warp >> 2;        // 0..1 (M warps, 32 rows each)
    const int wn = warp & 3;         // 0..3 (N warps, 32 cols each)
    const int qbase = blockIdx.x * TM;

    // ---- Prologue: Q tile + E chunk 0 in one cp.async group ----
    {
        const __half* gQH = g_QH + (size_t)qbase * CDIM;
        #pragma unroll
        for (int t = 0; t < 8; ++t) {
            int s = tid + t * 256;              // 2048 16B-segs
            int row = s >> 5, col = (s & 31) << 3;
            cp_async16(smem_u32(QHs + row * QST + col), gQH + row * CDIM + col);
        }
        #pragma unroll
        for (int t = 0; t < 4; ++t) {           // chunk 0: 128 rows x 128B
            int s = tid + t * 256;
            int row = s >> 3, col = (s & 7) << 3;
            cp_async16(smem_u32(EHs + row * EST + col), g_EH + row * CDIM + col);
        }
        cp_commit();
    }
    if (tid < TM) qsq_s[tid] = g_qsq[qbase + tid];

    float acc[2][4][4];
    float runMin[4], runMin2[4];
    int   runIdx[4];
    float qsq_r[4];
    #pragma unroll
    for (int r = 0; r < 4; ++r) {
        runMin[r] = FLT_MAX; runMin2[r] = FLT_MAX; runIdx[r] = 0;
    }

    const int a_row  = wm * 32 + (lane & 15);
    const int a_colb = (lane >> 4) << 3;
    const int b_n    = wn * 32 + (lane & 7) + ((lane >> 4) << 3);
    const int b_k    = ((lane >> 3) & 1) << 3;
    const int tl = lane & 3, gid = lane >> 2;

    for (int cc = 0; cc < NCHUNK; ++cc) {
        const int nt = cc >> 2, kt = cc & 3;
        cp_wait0();                // chunk cc resident
        __syncthreads();           // everyone done with buf (cc-1)&1
        if (cc == 0) {
            #pragma unroll
            for (int r = 0; r < 4; ++r)
                qsq_r[r] = qsq_s[wm * 32 + (r >> 1) * 16 + gid + (r & 1) * 8];
        }
        // prefetch next chunk into the other buffer
        if (cc + 1 < NCHUNK) {
            int nn = (cc + 1) >> 2, nk = (cc + 1) & 3;
            const __half* gEH = g_EH + (size_t)(nn * TN) * CDIM + nk * KT;
            __half* dEH = EHs + ((cc + 1) & 1) * (TN * EST);
            #pragma unroll
            for (int t = 0; t < 4; ++t) {
                int s = tid + t * 256;
                int row = s >> 3, col = (s & 7) << 3;
                cp_async16(smem_u32(dEH + row * EST + col), gEH + row * CDIM + col);
            }
            cp_commit();
        }
        if (kt == 0) {
            if (tid < TN) esq_s[tid] = g_esq[nt * TN + tid];
            #pragma unroll
            for (int i = 0; i < 2; ++i) {
                #pragma unroll
                for (int j = 0; j < 4; ++j) {
                    #pragma unroll
                    for (int c2 = 0; c2 < 4; ++c2) acc[i][j][c2] = 0.0f;
                }
            }
        }

        // ---- compute chunk: 4 k16-steps; per ks: 4 ldsm.x4 + 8 HMMA ----
        const __half* bEH = EHs + (cc & 1) * (TN * EST);
        #pragma unroll
        for (int ks = 0; ks < 4; ++ks) {
            uint32_t ah[2][4];
            #pragma unroll
            for (int i = 0; i < 2; ++i) {
                int col = kt * KT + ks * 16 + a_colb;
                ldsm4(ah[i][0], ah[i][1], ah[i][2], ah[i][3],
                      smem_u32(QHs + (a_row + i * 16) * QST + col));
            }
            #pragma unroll
            for (int jj = 0; jj < 2; ++jj) {
                uint32_t bh[4];
                int ecol = ks * 16 + b_k;
                ldsm4(bh[0], bh[1], bh[2], bh[3],
                      smem_u32(bEH + (b_n + jj * 16) * EST + ecol));
                #pragma unroll
                for (int i = 0; i < 2; ++i) {
                    mma16816(acc[i][jj*2+0], ah[i][0],ah[i][1],ah[i][2],ah[i][3], bh[0],bh[1]);
                    mma16816(acc[i][jj*2+1], ah[i][0],ah[i][1],ah[i][2],ah[i][3], bh[2],bh[3]);
                }
            }
        }

        if (kt == 3) {
            // Epilogue: ascending n within lane; strict '<' = first index.
            // -2^-9 folds the 1/1024 (=16*64) de-scale with the -2 factor.
            #pragma unroll
            for (int j = 0; j < 4; ++j) {
                int nloc = wn * 32 + j * 8 + tl * 2;
                float2 es = *(const float2*)(esq_s + nloc);
                int n0 = nt * TN + nloc;
                #pragma unroll
                for (int i = 0; i < 2; ++i) {
                    #pragma unroll
                    for (int h = 0; h < 2; ++h) {
                        int r = i * 2 + h;
                        float t0 = __fadd_rn(qsq_r[r], es.x);
                        float d  = __fmaf_rn(-0.001953125f, acc[i][j][h*2+0], t0);
                        if (d < runMin[r]) {
                            runMin2[r] = runMin[r];
                            runMin[r] = d; runIdx[r] = n0;
                        } else if (d < runMin2[r]) runMin2[r] = d;
                        t0 = __fadd_rn(qsq_r[r], es.y);
                        d  = __fmaf_rn(-0.001953125f, acc[i][j][h*2+1], t0);
                        if (d < runMin[r]) {
                            runMin2[r] = runMin[r];
                            runMin[r] = d; runIdx[r] = n0 + 1;
                        } else if (d < runMin2[r]) runMin2[r] = d;
                    }
                }
            }
        }
    }

    // ---- Cross-lane top-2 reduction: [64 rows][16 slots] ----
    __syncthreads();   // all compute + async copies done; safe to overlay
    {
        const int slot = wn * 4 + tl;
        #pragma unroll
        for (int r = 0; r < 4; ++r) {
            int m = wm * 32 + (r >> 1) * 16 + gid + (r & 1) * 8;
            redMin [m * 16 + slot] = runMin[r];
            redIdx [m * 16 + slot] = runIdx[r];
            redMin2[m * 16 + slot] = runMin2[r];
        }
    }
    __syncthreads();

    float myDist = 0.0f;
    if (tid < TM) {
        float m1 = FLT_MAX, m2 = FLT_MAX; int i1 = 0;
        #pragma unroll
        for (int s2 = 0; s2 < 16; ++s2) {
            float v1 = redMin [tid * 16 + s2];
            int   id = redIdx [tid * 16 + s2];
            float v2 = redMin2[tid * 16 + s2];
            if (v1 < m1 || (v1 == m1 && id < i1)) {
                m2 = (m1 < m2) ? m1 : m2;
                m1 = v1; i1 = id;
            } else {
                m2 = (v1 < m2) ? v1 : m2;
            }
            m2 = (v2 < m2) ? v2 : m2;
        }
        int q = qbase + tid;
        g_key[q]  = ~0ull;
        g_prov[q] = i1;
        if (m2 - m1 <= DELTA) {
            int slot = atomicAdd(&g_nflag, 1);
            g_flist[slot] = q;
        }
        myDist = m1;
    }
    #pragma unroll
    for (int off = 16; off; off >>= 1)
        myDist += __shfl_down_sync(0xffffffffu, myDist, off);
    if (lane == 0 && warp < 2) atomicAdd(&g_dist_sum, myDist);
}

// ---------------------------------------------------------------------------
// Pass 2: exact rescore, E-stationary. Each block owns a 128-code fp32 E
// tile in SMEM (loaded ONCE), then iterates over flagged queries 4 at a
// time; each thread handles (1 code, 2 queries) register-blocked.
// Arithmetic bit-identical to the verified Round-2 kernel.
// ---------------------------------------------------------------------------
__global__ void __launch_bounds__(256)
vq_rescore_kernel(const float* __restrict__ Q, const float* __restrict__ E) {
    extern __shared__ float rsm[];
    float* Es    = rsm;                        // [RC][RES_ST] padded
    float* Qs    = rsm + RC * RES_ST;          // [4][CDIM]
    float* qsq4  = Qs + 4 * CDIM;              // [4]
    float* esq_t = qsq4 + 8;                   // [RC]

    const int tid   = threadIdx.x;
    const int lane  = tid & 31;
    const int nbase = blockIdx.x * RC;
    const int c     = tid & (RC - 1);          // code within tile
    const int qh    = tid >> 7;                // 0/1: which query pair

    // Load E tile (float4, padded stride is 16B-aligned: 260*4 = 1040)
    for (int idx = tid; idx < RC * (CDIM / 4); idx += 256) {
        int r = idx >> 6, k4 = idx & 63;
        float4 v = reinterpret_cast<const float4*>(
            E + (size_t)(nbase + r) * CDIM)[k4];
        *reinterpret_cast<float4*>(Es + r * RES_ST + k4 * 4) = v;
    }
    if (tid < RC) esq_t[tid] = g_esq[nbase + tid];

    const int nf = g_nflag;
    for (int f0 = 0; f0 < nf; f0 += 4) {
        __syncthreads();   // previous iteration done reading Qs
        {
            int r = tid >> 6, k4 = tid & 63;
            if (f0 + r < nf) {
                float4 v = reinterpret_cast<const float4*>(
                    Q + (size_t)g_flist[f0 + r] * CDIM)[k4];
                *reinterpret_cast<float4*>(Qs + r * CDIM + k4 * 4) = v;
            }
            if (tid < 4 && f0 + tid < nf) qsq4[tid] = g_qsq[g_flist[f0 + tid]];
        }
        __syncthreads();

        const int q0i = f0 + qh * 2, q1i = q0i + 1;
        const bool v0 = (q0i < nf), v1 = (q1i < nf);
        const float* er  = Es + c * RES_ST;
        const float* qr0 = Qs + (qh * 2) * CDIM;
        const float* qr1 = qr0 + CDIM;
        float acc0 = 0.0f, acc1 = 0.0f;
        #pragma unroll 8
        for (int k4 = 0; k4 < 64; ++k4) {
            float4 e = *reinterpret_cast<const float4*>(er  + k4 * 4);
            float4 a = *reinterpret_cast<const float4*>(qr0 + k4 * 4);
            float4 b = *reinterpret_cast<const float4*>(qr1 + k4 * 4);
            acc0 = __fmaf_rn(a.x, e.x, acc0);
            acc0 = __fmaf_rn(a.y, e.y, acc0);
            acc0 = __fmaf_rn(a.z, e.z, acc0);
            acc0 = __fmaf_rn(a.w, e.w, acc0);
            acc1 = __fmaf_rn(b.x, e.x, acc1);
            acc1 = __fmaf_rn(b.y, e.y, acc1);
            acc1 = __fmaf_rn(b.z, e.z, acc1);
            acc1 = __fmaf_rn(b.w, e.w, acc1);
        }

        const int n = nbase + c;
        const float es = esq_t[c];
        unsigned long long key0 = ~0ull, key1 = ~0ull;
        if (v0) {
            float t0 = __fadd_rn(qsq4[qh * 2], es);
            float d  = __fmaf_rn(-2.0f, acc0, t0);   // d > 0 always here
            key0 = ((unsigned long long)__float_as_uint(d) << 32) | (unsigned)n;
        }
        if (v1) {
            float t0 = __fadd_rn(qsq4[qh * 2 + 1], es);
            float d  = __fmaf_rn(-2.0f, acc1, t0);
            key1 = ((unsigned long long)__float_as_uint(d) << 32) | (unsigned)n;
        }
        // warp min-reduce (all lanes in a warp share the same query pair)
        #pragma unroll
        for (int off = 16; off; off >>= 1) {
            unsigned long long o0 = __shfl_down_sync(0xffffffffu, key0, off);
            unsigned long long o1 = __shfl_down_sync(0xffffffffu, key1, off);
            key0 = (o0 < key0) ? o0 : key0;
            key1 = (o1 < key1) ? o1 : key1;
        }
        if (lane == 0) {
            if (v0) atomicMin(&g_key[g_flist[q0i]], key0);
            if (v1) atomicMin(&g_key[g_flist[q1i]], key1);
        }
    }
}

// ---------------------------------------------------------------------------
// Pass 3: finalize indices + gather quantized rows + loss scalar.
// One warp per query.
// ---------------------------------------------------------------------------
__global__ void __launch_bounds__(256)
vq_final3_kernel(const float* __restrict__ E, float* __restrict__ out,
                 float* __restrict__ out_loss) {
    if (blockIdx.x == 0 && threadIdx.x == 0)
        *out_loss = 1.25f * g_dist_sum * (1.0f / ((float)NQ * (float)CDIM));
    const int q    = blockIdx.x * 8 + (threadIdx.x >> 5);
    const int lane = threadIdx.x & 31;
    unsigned long long k = g_key[q];
    int idx = (k != ~0ull) ? (int)(k & 0xffffffffu) : g_prov[q];
    if (lane == 0) out[q] = (float)idx;
    const float4* src = reinterpret_cast<const float4*>(E + (size_t)idx * CDIM);
    float4* dst = reinterpret_cast<float4*>(out + NQ + (size_t)q * CDIM);
    dst[lane]      = src[lane];
    dst[lane + 32] = src[lane + 32];
}

extern "C" void kernel_launch(void* const* d_in, const int* in_sizes, int n_in,
                              void* d_out, int out_size) {
    const float* Q = (const float*)d_in[0];
    const float* E = (const float*)d_in[1];
    float* out = (float*)d_out;

    cudaFuncSetAttribute(vq_main_kernel,
                         cudaFuncAttributeMaxDynamicSharedMemorySize,
                         SMEM_TOTAL);
    cudaFuncSetAttribute(vq_rescore_kernel,
                         cudaFuncAttributeMaxDynamicSharedMemorySize,
                         RSMEM);

    vq_prep_kernel<<<(NC + NQ) / 8, 256>>>(Q, E);
    vq_main_kernel<<<NQ / TM, 256, SMEM_TOTAL>>>();
    vq_rescore_kernel<<<NC / RC, 256, RSMEM>>>(Q, E);
    vq_final3_kernel<<<NQ / 8, 256>>>(E, out, out + out_size - 1);
}

// round 11
// speedup vs baseline: 3.6297x; 2.0231x over previous
#include <cuda_runtime.h>
#include <cuda_fp16.h>
#include <cstdint>
#include <float.h>

// Problem constants (fixed shapes from reference setup_inputs)
constexpr int NQ   = 16384;
constexpr int NC   = 8192;
constexpr int CDIM = 256;
constexpr int TM   = 64;        // queries per block (pass 1)
constexpr int TN   = 128;       // codes per n-tile
constexpr int KT   = 64;        // k-halves per E chunk
constexpr int QST  = 264;       // Q smem row stride (halves)
constexpr int EST  = 72;        // E chunk smem row stride (halves)
constexpr int NTILES = NC / TN;        // 64
constexpr int NCHUNK = NTILES * 4;     // 256 chunks

// Rescue margin: single-pass fp16 distance error sd ~1.8e-4 -> 2e-3 ~ 2x6sigma.
constexpr float DELTA = 2.0e-3f;

// SMEM byte offsets (pass-1 main kernel)
constexpr int OFF_QH  = 0;                  // 64*264*2  = 33792
constexpr int OFF_EH  = 33792;              // 2 bufs * 128*72*2 = 36864
constexpr int OFF_ESQ = 70656;              // 128 floats
constexpr int OFF_QSQ = 71168;              // 64 floats
constexpr int SMEM_TOTAL = 71424;

// Rescore kernel geometry (v3: query-parallel + 4x4 register blocking)
constexpr int RC     = 128;                 // codes per rescore block
constexpr int RES_ST = 260;                 // padded fp32 row stride (floats)
constexpr int QB     = 32;                  // flagged queries per step
constexpr int QG     = 8;                   // query groups (grid.y)
constexpr int RSMEM  = (RC * RES_ST + QB * CDIM + QB + RC) * 4;  // ~163 KB

__device__ __half g_QH[NQ * CDIM];
__device__ __half g_EH[NC * CDIM];
__device__ float  g_esq[NC];
__device__ float  g_qsq[NQ];
__device__ float  g_dist_sum;
__device__ int    g_prov[NQ];                  // provisional winner (pass 1)
__device__ unsigned long long g_key[NQ];       // rescored (dist,idx) key
__device__ int    g_flist[NQ];                 // flagged query list
__device__ int    g_nflag;

// ---------------------------------------------------------------------------
__device__ __forceinline__ void two_sum(float a, float b, float& s, float& e) {
    s = a + b;
    float bp = s - a;
    e = (a - (s - bp)) + (b - bp);
}

// ---------------------------------------------------------------------------
// Fused prep: init + fp16 convert (exact pow2 pre-scale) + compensated sumsq.
// One warp per 256-float row.
// ---------------------------------------------------------------------------
__global__ void vq_prep_kernel(const float* __restrict__ Q,
                               const float* __restrict__ E) {
    if (blockIdx.x == 0 && threadIdx.x == 0) {
        g_dist_sum = 0.0f;
        g_nflag = 0;
    }
    const int gwarp = (blockIdx.x * blockDim.x + threadIdx.x) >> 5;
    const int lane  = threadIdx.x & 31;
    if (gwarp >= NC + NQ) return;

    const bool isE = (gwarp < NC);
    const float* src = isE ? (E + (size_t)gwarp * CDIM)
                           : (Q + (size_t)(gwarp - NC) * CDIM);
    const float scale = isE ? 64.0f : 16.0f;
    __half* dst = isE ? (g_EH + (size_t)gwarp * CDIM)
                      : (g_QH + (size_t)(gwarp - NC) * CDIM);

    float4 a = reinterpret_cast<const float4*>(src)[lane];
    float4 b = reinterpret_cast<const float4*>(src)[lane + 32];

    {
        __half2 h[4];
        h[0] = __floats2half2_rn(a.x * scale, a.y * scale);
        h[1] = __floats2half2_rn(a.z * scale, a.w * scale);
        h[2] = __floats2half2_rn(b.x * scale, b.y * scale);
        h[3] = __floats2half2_rn(b.z * scale, b.w * scale);
        const uint2* p = reinterpret_cast<const uint2*>(h);
        *reinterpret_cast<uint2*>(dst + lane * 4)       = p[0];
        *reinterpret_cast<uint2*>(dst + 128 + lane * 4) = p[1];
    }

    float v[8] = {a.x, a.y, a.z, a.w, b.x, b.y, b.z, b.w};
    float s = 0.0f, c = 0.0f;
    #pragma unroll
    for (int k = 0; k < 8; ++k) {
        float p = v[k] * v[k];
        float r = __fmaf_rn(v[k], v[k], -p);
        float t, e;
        two_sum(s, p, t, e);
        s = t; c += e + r;
    }
    #pragma unroll
    for (int off = 16; off; off >>= 1) {
        float so = __shfl_down_sync(0xffffffffu, s, off);
        float co = __shfl_down_sync(0xffffffffu, c, off);
        float t, e;
        two_sum(s, so, t, e);
        s = t; c += e + co;
    }
    if (lane == 0) {
        float total = s + c;
        if (isE) g_esq[gwarp]      = total;
        else     g_qsq[gwarp - NC] = total;
    }
}

// ---------------------------------------------------------------------------
// PTX helpers
// ---------------------------------------------------------------------------
__device__ __forceinline__ uint32_t smem_u32(const void* p) {
    return (uint32_t)__cvta_generic_to_shared(p);
}
__device__ __forceinline__ void ldsm4(uint32_t& r0, uint32_t& r1,
                                      uint32_t& r2, uint32_t& r3, uint32_t a) {
    asm volatile("ldmatrix.sync.aligned.m8n8.x4.shared.b16 {%0,%1,%2,%3},[%4];"
                 : "=r"(r0), "=r"(r1), "=r"(r2), "=r"(r3) : "r"(a));
}
__device__ __forceinline__ void mma16816(float* c,
                                         uint32_t a0, uint32_t a1,
                                         uint32_t a2, uint32_t a3,
                                         uint32_t b0, uint32_t b1) {
    asm("mma.sync.aligned.m16n8k16.row.col.f32.f16.f16.f32 "
        "{%0,%1,%2,%3},{%4,%5,%6,%7},{%8,%9},{%0,%1,%2,%3};"
        : "+f"(c[0]), "+f"(c[1]), "+f"(c[2]), "+f"(c[3])
        : "r"(a0), "r"(a1), "r"(a2), "r"(a3), "r"(b0), "r"(b1));
}
__device__ __forceinline__ void cp_async16(uint32_t s, const void* g) {
    asm volatile("cp.async.cg.shared.global [%0],[%1],16;" :: "r"(s), "l"(g));
}
__device__ __forceinline__ void cp_commit() {
    asm volatile("cp.async.commit_group;");
}
__device__ __forceinline__ void cp_wait0() {
    asm volatile("cp.async.wait_group 0;" ::: "memory");
}

// ---------------------------------------------------------------------------
// Pass 1: single-pass fp16 tensor-core distance GEMM + top-2 + flagging.
// (R10-verified; unchanged this round.)
// ---------------------------------------------------------------------------
__global__ void __launch_bounds__(256, 2)
vq_main_kernel() {
    extern __shared__ char smem[];
    __half* QHs   = (__half*)(smem + OFF_QH);
    __half* EHs   = (__half*)(smem + OFF_EH);
    float*  esq_s = (float*)(smem + OFF_ESQ);
    float*  qsq_s = (float*)(smem + OFF_QSQ);
    // overlay (used only after the main loop, behind a barrier)
    float*  redMin  = (float*)(smem + OFF_EH);
    int*    redIdx  = (int*)  (smem + OFF_EH + 4096);
    float*  redMin2 = (float*)(smem + OFF_EH + 8192);

    const int tid  = threadIdx.x;
    const int lane = tid & 31;
    const int warp = tid >> 5;
    const int wm = warp >> 2;        // 0..1 (M warps, 32 rows each)
    const int wn = warp & 3;         // 0..3 (N warps, 32 cols each)
    const int qbase = blockIdx.x * TM;

    // ---- Prologue: Q tile + E chunk 0 in one cp.async group ----
    {
        const __half* gQH = g_QH + (size_t)qbase * CDIM;
        #pragma unroll
        for (int t = 0; t < 8; ++t) {
            int s = tid + t * 256;              // 2048 16B-segs
            int row = s >> 5, col = (s & 31) << 3;
            cp_async16(smem_u32(QHs + row * QST + col), gQH + row * CDIM + col);
        }
        #pragma unroll
        for (int t = 0; t < 4; ++t) {           // chunk 0: 128 rows x 128B
            int s = tid + t * 256;
            int row = s >> 3, col = (s & 7) << 3;
            cp_async16(smem_u32(EHs + row * EST + col), g_EH + row * CDIM + col);
        }
        cp_commit();
    }
    if (tid < TM) qsq_s[tid] = g_qsq[qbase + tid];

    float acc[2][4][4];
    float runMin[4], runMin2[4];
    int   runIdx[4];
    float qsq_r[4];
    #pragma unroll
    for (int r = 0; r < 4; ++r) {
        runMin[r] = FLT_MAX; runMin2[r] = FLT_MAX; runIdx[r] = 0;
    }

    const int a_row  = wm * 32 + (lane & 15);
    const int a_colb = (lane >> 4) << 3;
    const int b_n    = wn * 32 + (lane & 7) + ((lane >> 4) << 3);
    const int b_k    = ((lane >> 3) & 1) << 3;
    const int tl = lane & 3, gid = lane >> 2;

    for (int cc = 0; cc < NCHUNK; ++cc) {
        const int nt = cc >> 2, kt = cc & 3;
        cp_wait0();                // chunk cc resident
        __syncthreads();           // everyone done with buf (cc-1)&1
        if (cc == 0) {
            #pragma unroll
            for (int r = 0; r < 4; ++r)
                qsq_r[r] = qsq_s[wm * 32 + (r >> 1) * 16 + gid + (r & 1) * 8];
        }
        // prefetch next chunk into the other buffer
        if (cc + 1 < NCHUNK) {
            int nn = (cc + 1) >> 2, nk = (cc + 1) & 3;
            const __half* gEH = g_EH + (size_t)(nn * TN) * CDIM + nk * KT;
            __half* dEH = EHs + ((cc + 1) & 1) * (TN * EST);
            #pragma unroll
            for (int t = 0; t < 4; ++t) {
                int s = tid + t * 256;
                int row = s >> 3, col = (s & 7) << 3;
                cp_async16(smem_u32(dEH + row * EST + col), gEH + row * CDIM + col);
            }
            cp_commit();
        }
        if (kt == 0) {
            if (tid < TN) esq_s[tid] = g_esq[nt * TN + tid];
            #pragma unroll
            for (int i = 0; i < 2; ++i) {
                #pragma unroll
                for (int j = 0; j < 4; ++j) {
                    #pragma unroll
                    for (int c2 = 0; c2 < 4; ++c2) acc[i][j][c2] = 0.0f;
                }
            }
        }

        // ---- compute chunk: 4 k16-steps; per ks: 4 ldsm.x4 + 8 HMMA ----
        const __half* bEH = EHs + (cc & 1) * (TN * EST);
        #pragma unroll
        for (int ks = 0; ks < 4; ++ks) {
            uint32_t ah[2][4];
            #pragma unroll
            for (int i = 0; i < 2; ++i) {
                int col = kt * KT + ks * 16 + a_colb;
                ldsm4(ah[i][0], ah[i][1], ah[i][2], ah[i][3],
                      smem_u32(QHs + (a_row + i * 16) * QST + col));
            }
            #pragma unroll
            for (int jj = 0; jj < 2; ++jj) {
                uint32_t bh[4];
                int ecol = ks * 16 + b_k;
                ldsm4(bh[0], bh[1], bh[2], bh[3],
                      smem_u32(bEH + (b_n + jj * 16) * EST + ecol));
                #pragma unroll
                for (int i = 0; i < 2; ++i) {
                    mma16816(acc[i][jj*2+0], ah[i][0],ah[i][1],ah[i][2],ah[i][3], bh[0],bh[1]);
                    mma16816(acc[i][jj*2+1], ah[i][0],ah[i][1],ah[i][2],ah[i][3], bh[2],bh[3]);
                }
            }
        }

        if (kt == 3) {
            // Epilogue: ascending n within lane; strict '<' = first index.
            // -2^-9 folds the 1/1024 (=16*64) de-scale with the -2 factor.
            #pragma unroll
            for (int j = 0; j < 4; ++j) {
                int nloc = wn * 32 + j * 8 + tl * 2;
                float2 es = *(const float2*)(esq_s + nloc);
                int n0 = nt * TN + nloc;
                #pragma unroll
                for (int i = 0; i < 2; ++i) {
                    #pragma unroll
                    for (int h = 0; h < 2; ++h) {
                        int r = i * 2 + h;
                        float t0 = __fadd_rn(qsq_r[r], es.x);
                        float d  = __fmaf_rn(-0.001953125f, acc[i][j][h*2+0], t0);
                        if (d < runMin[r]) {
                            runMin2[r] = runMin[r];
                            runMin[r] = d; runIdx[r] = n0;
                        } else if (d < runMin2[r]) runMin2[r] = d;
                        t0 = __fadd_rn(qsq_r[r], es.y);
                        d  = __fmaf_rn(-0.001953125f, acc[i][j][h*2+1], t0);
                        if (d < runMin[r]) {
                            runMin2[r] = runMin[r];
                            runMin[r] = d; runIdx[r] = n0 + 1;
                        } else if (d < runMin2[r]) runMin2[r] = d;
                    }
                }
            }
        }
    }

    // ---- Cross-lane top-2 reduction: [64 rows][16 slots] ----
    __syncthreads();   // all compute + async copies done; safe to overlay
    {
        const int slot = wn * 4 + tl;
        #pragma unroll
        for (int r = 0; r < 4; ++r) {
            int m = wm * 32 + (r >> 1) * 16 + gid + (r & 1) * 8;
            redMin [m * 16 + slot] = runMin[r];
            redIdx [m * 16 + slot] = runIdx[r];
            redMin2[m * 16 + slot] = runMin2[r];
        }
    }
    __syncthreads();

    float myDist = 0.0f;
    if (tid < TM) {
        float m1 = FLT_MAX, m2 = FLT_MAX; int i1 = 0;
        #pragma unroll
        for (int s2 = 0; s2 < 16; ++s2) {
            float v1 = redMin [tid * 16 + s2];
            int   id = redIdx [tid * 16 + s2];
            float v2 = redMin2[tid * 16 + s2];
            if (v1 < m1 || (v1 == m1 && id < i1)) {
                m2 = (m1 < m2) ? m1 : m2;
                m1 = v1; i1 = id;
            } else {
                m2 = (v1 < m2) ? v1 : m2;
            }
            m2 = (v2 < m2) ? v2 : m2;
        }
        int q = qbase + tid;
        g_key[q]  = ~0ull;
        g_prov[q] = i1;
        if (m2 - m1 <= DELTA) {
            int slot = atomicAdd(&g_nflag, 1);
            g_flist[slot] = q;
        }
        myDist = m1;
    }
    #pragma unroll
    for (int off = 16; off; off >>= 1)
        myDist += __shfl_down_sync(0xffffffffu, myDist, off);
    if (lane == 0 && warp < 2) atomicAdd(&g_dist_sum, myDist);
}

// ---------------------------------------------------------------------------
// Pass 2 (v3): exact rescore, E-stationary + query-parallel.
// grid = (NC/RC, QG). Block owns a 128-code fp32 E tile in SMEM (loaded
// once); its query group processes 32 flagged queries per step. Each thread:
// 4 queries (warp-uniform) x 4 codes, 16 fp32 chains — bit-identical to the
// verified Round-2 arithmetic (ascending-k FMA chain, fl(fl(qsq+esq)-2dot)),
// first-index ties via atomicMin on (dist_bits<<32 | idx).
// ---------------------------------------------------------------------------
__global__ void __launch_bounds__(256)
vq_rescore_kernel(const float* __restrict__ Q, const float* __restrict__ E) {
    extern __shared__ float rsm[];
    float* Es    = rsm;                        // [RC][RES_ST] padded
    float* Qs    = rsm + RC * RES_ST;          // [QB][CDIM]
    float* qsq_s = Qs + QB * CDIM;             // [QB]
    float* esq_t = qsq_s + QB;                 // [RC]

    const int tid   = threadIdx.x;
    const int lane  = tid & 31;
    const int wq    = tid >> 5;                // warp -> query quad (0..7)
    const int nbase = blockIdx.x * RC;
    const int grp   = blockIdx.y;

    // Load E tile once (conflict-free: stride 260 floats)
    for (int idx = tid; idx < RC * (CDIM / 4); idx += 256) {
        int r = idx >> 6, k4 = idx & 63;
        float4 v = reinterpret_cast<const float4*>(
            E + (size_t)(nbase + r) * CDIM)[k4];
        *reinterpret_cast<float4*>(Es + r * RES_ST + k4 * 4) = v;
    }
    if (tid < RC) esq_t[tid] = g_esq[nbase + tid];

    const int nf = g_nflag;
    for (int f0 = grp * QB; f0 < nf; f0 += QG * QB) {
        __syncthreads();   // previous step done reading Qs
        for (int idx = tid; idx < QB * (CDIM / 4); idx += 256) {
            int r = idx >> 6, k4 = idx & 63;
            if (f0 + r < nf) {
                float4 v = reinterpret_cast<const float4*>(
                    Q + (size_t)g_flist[f0 + r] * CDIM)[k4];
                *reinterpret_cast<float4*>(Qs + r * CDIM + k4 * 4) = v;
            }
        }
        if (tid < QB && f0 + tid < nf) qsq_s[tid] = g_qsq[g_flist[f0 + tid]];
        __syncthreads();

        // 4 queries (wq*4..+3, warp-uniform) x 4 codes (lane+32c)
        float acc[4][4];
        #pragma unroll
        for (int qi = 0; qi < 4; ++qi)
            #pragma unroll
            for (int ci = 0; ci < 4; ++ci) acc[qi][ci] = 0.0f;

        const float* qr = Qs + (wq * 4) * CDIM;
        const float* er = Es + lane * RES_ST;
        #pragma unroll 2
        for (int k4 = 0; k4 < 64; ++k4) {
            float4 e0 = *reinterpret_cast<const float4*>(er + 0 * 32 * RES_ST + k4 * 4);
            float4 e1 = *reinterpret_cast<const float4*>(er + 1 * 32 * RES_ST + k4 * 4);
            float4 e2 = *reinterpret_cast<const float4*>(er + 2 * 32 * RES_ST + k4 * 4);
            float4 e3 = *reinterpret_cast<const float4*>(er + 3 * 32 * RES_ST + k4 * 4);
            #pragma unroll
            for (int qi = 0; qi < 4; ++qi) {
                float4 qv = *reinterpret_cast<const float4*>(
                    qr + qi * CDIM + k4 * 4);
                acc[qi][0] = __fmaf_rn(qv.x, e0.x, acc[qi][0]);
                acc[qi][0] = __fmaf_rn(qv.y, e0.y, acc[qi][0]);
                acc[qi][0] = __fmaf_rn(qv.z, e0.z, acc[qi][0]);
                acc[qi][0] = __fmaf_rn(qv.w, e0.w, acc[qi][0]);
                acc[qi][1] = __fmaf_rn(qv.x, e1.x, acc[qi][1]);
                acc[qi][1] = __fmaf_rn(qv.y, e1.y, acc[qi][1]);
                acc[qi][1] = __fmaf_rn(qv.z, e1.z, acc[qi][1]);
                acc[qi][1] = __fmaf_rn(qv.w, e1.w, acc[qi][1]);
                acc[qi][2] = __fmaf_rn(qv.x, e2.x, acc[qi][2]);
                acc[qi][2] = __fmaf_rn(qv.y, e2.y, acc[qi][2]);
                acc[qi][2] = __fmaf_rn(qv.z, e2.z, acc[qi][2]);
                acc[qi][2] = __fmaf_rn(qv.w, e2.w, acc[qi][2]);
                acc[qi][3] = __fmaf_rn(qv.x, e3.x, acc[qi][3]);
                acc[qi][3] = __fmaf_rn(qv.y, e3.y, acc[qi][3]);
                acc[qi][3] = __fmaf_rn(qv.z, e3.z, acc[qi][3]);
                acc[qi][3] = __fmaf_rn(qv.w, e3.w, acc[qi][3]);
            }
        }

        #pragma unroll
        for (int qi = 0; qi < 4; ++qi) {
            int fq = f0 + wq * 4 + qi;         // warp-uniform
            if (fq >= nf) break;
            float qs = qsq_s[wq * 4 + qi];
            unsigned long long best = ~0ull;
            #pragma unroll
            for (int ci = 0; ci < 4; ++ci) {
                int n = nbase + lane + ci * 32;
                float t0 = __fadd_rn(qs, esq_t[lane + ci * 32]);
                float d  = __fmaf_rn(-2.0f, acc[qi][ci], t0);   // d > 0
                unsigned long long key =
                    ((unsigned long long)__float_as_uint(d) << 32) | (unsigned)n;
                best = (key < best) ? key : best;
            }
            #pragma unroll
            for (int off = 16; off; off >>= 1) {
                unsigned long long o =
                    __shfl_down_sync(0xffffffffu, best, off);
                best = (o < best) ? o : best;
            }
            if (lane == 0) atomicMin(&g_key[g_flist[fq]], best);
        }
    }
}

// ---------------------------------------------------------------------------
// Pass 3: finalize indices + gather quantized rows + loss scalar.
// One warp per query.
// ---------------------------------------------------------------------------
__global__ void __launch_bounds__(256)
vq_final3_kernel(const float* __restrict__ E, float* __restrict__ out,
                 float* __restrict__ out_loss) {
    if (blockIdx.x == 0 && threadIdx.x == 0)
        *out_loss = 1.25f * g_dist_sum * (1.0f / ((float)NQ * (float)CDIM));
    const int q    = blockIdx.x * 8 + (threadIdx.x >> 5);
    const int lane = threadIdx.x & 31;
    unsigned long long k = g_key[q];
    int idx = (k != ~0ull) ? (int)(k & 0xffffffffu) : g_prov[q];
    if (lane == 0) out[q] = (float)idx;
    const float4* src = reinterpret_cast<const float4*>(E + (size_t)idx * CDIM);
    float4* dst = reinterpret_cast<float4*>(out + NQ + (size_t)q * CDIM);
    dst[lane]      = src[lane];
    dst[lane + 32] = src[lane + 32];
}

extern "C" void kernel_launch(void* const* d_in, const int* in_sizes, int n_in,
                              void* d_out, int out_size) {
    const float* Q = (const float*)d_in[0];
    const float* E = (const float*)d_in[1];
    float* out = (float*)d_out;

    cudaFuncSetAttribute(vq_main_kernel,
                         cudaFuncAttributeMaxDynamicSharedMemorySize,
                         SMEM_TOTAL);
    cudaFuncSetAttribute(vq_rescore_kernel,
                         cudaFuncAttributeMaxDynamicSharedMemorySize,
                         RSMEM);

    vq_prep_kernel<<<(NC + NQ) / 8, 256>>>(Q, E);
    vq_main_kernel<<<NQ / TM, 256, SMEM_TOTAL>>>();
    vq_rescore_kernel<<<dim3(NC / RC, QG), 256, RSMEM>>>(Q, E);
    vq_final3_kernel<<<NQ / 8, 256>>>(E, out, out + out_size - 1);
}

// round 12
// speedup vs baseline: 3.6996x; 1.0192x over previous
#include <cuda_runtime.h>
#include <cuda_fp16.h>
#include <cstdint>
#include <float.h>

// Problem constants (fixed shapes from reference setup_inputs)
constexpr int NQ   = 16384;
constexpr int NC   = 8192;
constexpr int CDIM = 256;
constexpr int TM   = 64;        // queries per block (pass 1)
constexpr int TN   = 128;       // codes per n-tile
constexpr int KT   = 128;       // k-halves per E chunk (doubled: fewer barriers)
constexpr int QST  = 264;       // Q smem row stride (halves)
constexpr int EST  = 136;       // E chunk smem row stride (halves), 272B
constexpr int NTILES = NC / TN;        // 64
constexpr int NCHUNK = NTILES * 2;     // 128 chunks (2 k-chunks per n-tile)

// Rescue margin: single-pass fp16 distance error sd ~1.8e-4 -> 2e-3 ~ 2x6sigma.
constexpr float DELTA = 2.0e-3f;

// SMEM byte offsets (pass-1 main kernel)
constexpr int OFF_QH  = 0;                  // 64*264*2  = 33792
constexpr int OFF_EH  = 33792;              // 2 bufs * 128*136*2 = 69632
constexpr int OFF_ESQ = 103424;             // 128 floats
constexpr int OFF_QSQ = 103936;             // 64 floats
constexpr int SMEM_TOTAL = 104192;          // x2 CTAs = 208384 < 228KB

// Rescore kernel geometry (v3: query-parallel + 4x4 register blocking)
constexpr int RC     = 128;                 // codes per rescore block
constexpr int RES_ST = 260;                 // padded fp32 row stride (floats)
constexpr int QB     = 32;                  // flagged queries per step
constexpr int QG     = 8;                   // query groups (grid.y)
constexpr int RSMEM  = (RC * RES_ST + QB * CDIM + QB + RC) * 4;  // ~163 KB

__device__ __half g_QH[NQ * CDIM];
__device__ __half g_EH[NC * CDIM];
__device__ float  g_esq[NC];
__device__ float  g_qsq[NQ];
__device__ float  g_dist_sum;
__device__ int    g_prov[NQ];                  // provisional winner (pass 1)
__device__ unsigned long long g_key[NQ];       // rescored (dist,idx) key
__device__ int    g_flist[NQ];                 // flagged query list
__device__ int    g_nflag;

// ---------------------------------------------------------------------------
__device__ __forceinline__ void two_sum(float a, float b, float& s, float& e) {
    s = a + b;
    float bp = s - a;
    e = (a - (s - bp)) + (b - bp);
}

// ---------------------------------------------------------------------------
// Fused prep: init + fp16 convert (exact pow2 pre-scale) + compensated sumsq.
// One warp per 256-float row.
// ---------------------------------------------------------------------------
__global__ void vq_prep_kernel(const float* __restrict__ Q,
                               const float* __restrict__ E) {
    if (blockIdx.x == 0 && threadIdx.x == 0) {
        g_dist_sum = 0.0f;
        g_nflag = 0;
    }
    const int gwarp = (blockIdx.x * blockDim.x + threadIdx.x) >> 5;
    const int lane  = threadIdx.x & 31;
    if (gwarp >= NC + NQ) return;

    const bool isE = (gwarp < NC);
    const float* src = isE ? (E + (size_t)gwarp * CDIM)
                           : (Q + (size_t)(gwarp - NC) * CDIM);
    const float scale = isE ? 64.0f : 16.0f;
    __half* dst = isE ? (g_EH + (size_t)gwarp * CDIM)
                      : (g_QH + (size_t)(gwarp - NC) * CDIM);

    float4 a = reinterpret_cast<const float4*>(src)[lane];
    float4 b = reinterpret_cast<const float4*>(src)[lane + 32];

    {
        __half2 h[4];
        h[0] = __floats2half2_rn(a.x * scale, a.y * scale);
        h[1] = __floats2half2_rn(a.z * scale, a.w * scale);
        h[2] = __floats2half2_rn(b.x * scale, b.y * scale);
        h[3] = __floats2half2_rn(b.z * scale, b.w * scale);
        const uint2* p = reinterpret_cast<const uint2*>(h);
        *reinterpret_cast<uint2*>(dst + lane * 4)       = p[0];
        *reinterpret_cast<uint2*>(dst + 128 + lane * 4) = p[1];
    }

    float v[8] = {a.x, a.y, a.z, a.w, b.x, b.y, b.z, b.w};
    float s = 0.0f, c = 0.0f;
    #pragma unroll
    for (int k = 0; k < 8; ++k) {
        float p = v[k] * v[k];
        float r = __fmaf_rn(v[k], v[k], -p);
        float t, e;
        two_sum(s, p, t, e);
        s = t; c += e + r;
    }
    #pragma unroll
    for (int off = 16; off; off >>= 1) {
        float so = __shfl_down_sync(0xffffffffu, s, off);
        float co = __shfl_down_sync(0xffffffffu, c, off);
        float t, e;
        two_sum(s, so, t, e);
        s = t; c += e + co;
    }
    if (lane == 0) {
        float total = s + c;
        if (isE) g_esq[gwarp]      = total;
        else     g_qsq[gwarp - NC] = total;
    }
}

// ---------------------------------------------------------------------------
// PTX helpers
// ---------------------------------------------------------------------------
__device__ __forceinline__ uint32_t smem_u32(const void* p) {
    return (uint32_t)__cvta_generic_to_shared(p);
}
__device__ __forceinline__ void ldsm4(uint32_t& r0, uint32_t& r1,
                                      uint32_t& r2, uint32_t& r3, uint32_t a) {
    asm volatile("ldmatrix.sync.aligned.m8n8.x4.shared.b16 {%0,%1,%2,%3},[%4];"
                 : "=r"(r0), "=r"(r1), "=r"(r2), "=r"(r3) : "r"(a));
}
__device__ __forceinline__ void mma16816(float* c,
                                         uint32_t a0, uint32_t a1,
                                         uint32_t a2, uint32_t a3,
                                         uint32_t b0, uint32_t b1) {
    asm("mma.sync.aligned.m16n8k16.row.col.f32.f16.f16.f32 "
        "{%0,%1,%2,%3},{%4,%5,%6,%7},{%8,%9},{%0,%1,%2,%3};"
        : "+f"(c[0]), "+f"(c[1]), "+f"(c[2]), "+f"(c[3])
        : "r"(a0), "r"(a1), "r"(a2), "r"(a3), "r"(b0), "r"(b1));
}
__device__ __forceinline__ void cp_async16(uint32_t s, const void* g) {
    asm volatile("cp.async.cg.shared.global [%0],[%1],16;" :: "r"(s), "l"(g));
}
__device__ __forceinline__ void cp_commit() {
    asm volatile("cp.async.commit_group;");
}
__device__ __forceinline__ void cp_wait0() {
    asm volatile("cp.async.wait_group 0;" ::: "memory");
}

// ---------------------------------------------------------------------------
// Pass 1: single-pass fp16 tensor-core distance GEMM + top-2 + flagging.
// KT=128: each chunk is a full 128-row x 128-half E slab; 8 k16-steps per
// barrier (double R11's compute window per sync). Fragment maps unchanged.
// ---------------------------------------------------------------------------
__global__ void __launch_bounds__(256, 2)
vq_main_kernel() {
    extern __shared__ char smem[];
    __half* QHs   = (__half*)(smem + OFF_QH);
    __half* EHs   = (__half*)(smem + OFF_EH);
    float*  esq_s = (float*)(smem + OFF_ESQ);
    float*  qsq_s = (float*)(smem + OFF_QSQ);
    // overlay (used only after the main loop, behind a barrier)
    float*  redMin  = (float*)(smem + OFF_EH);
    int*    redIdx  = (int*)  (smem + OFF_EH + 4096);
    float*  redMin2 = (float*)(smem + OFF_EH + 8192);

    const int tid  = threadIdx.x;
    const int lane = tid & 31;
    const int warp = tid >> 5;
    const int wm = warp >> 2;        // 0..1 (M warps, 32 rows each)
    const int wn = warp & 3;         // 0..3 (N warps, 32 cols each)
    const int qbase = blockIdx.x * TM;

    // ---- Prologue: Q tile + E chunk 0 in one cp.async group ----
    {
        const __half* gQH = g_QH + (size_t)qbase * CDIM;
        #pragma unroll
        for (int t = 0; t < 8; ++t) {
            int s = tid + t * 256;              // 2048 16B-segs
            int row = s >> 5, col = (s & 31) << 3;
            cp_async16(smem_u32(QHs + row * QST + col), gQH + row * CDIM + col);
        }
        #pragma unroll
        for (int t = 0; t < 8; ++t) {           // chunk 0: 128 rows x 256B
            int s = tid + t * 256;
            int row = s >> 4, col = (s & 15) << 3;
            cp_async16(smem_u32(EHs + row * EST + col), g_EH + row * CDIM + col);
        }
        cp_commit();
    }
    if (tid < TM) qsq_s[tid] = g_qsq[qbase + tid];

    float acc[2][4][4];
    float runMin[4], runMin2[4];
    int   runIdx[4];
    float qsq_r[4];
    #pragma unroll
    for (int r = 0; r < 4; ++r) {
        runMin[r] = FLT_MAX; runMin2[r] = FLT_MAX; runIdx[r] = 0;
    }

    const int a_row  = wm * 32 + (lane & 15);
    const int a_colb = (lane >> 4) << 3;
    const int b_n    = wn * 32 + (lane & 7) + ((lane >> 4) << 3);
    const int b_k    = ((lane >> 3) & 1) << 3;
    const int tl = lane & 3, gid = lane >> 2;

    for (int cc = 0; cc < NCHUNK; ++cc) {
        const int nt = cc >> 1, kt = cc & 1;
        cp_wait0();                // chunk cc resident
        __syncthreads();           // everyone done with buf (cc-1)&1
        if (cc == 0) {
            #pragma unroll
            for (int r = 0; r < 4; ++r)
                qsq_r[r] = qsq_s[wm * 32 + (r >> 1) * 16 + gid + (r & 1) * 8];
        }
        // prefetch next chunk into the other buffer
        if (cc + 1 < NCHUNK) {
            int nn = (cc + 1) >> 1, nk = (cc + 1) & 1;
            const __half* gEH = g_EH + (size_t)(nn * TN) * CDIM + nk * KT;
            __half* dEH = EHs + ((cc + 1) & 1) * (TN * EST);
            #pragma unroll
            for (int t = 0; t < 8; ++t) {
                int s = tid + t * 256;
                int row = s >> 4, col = (s & 15) << 3;
                cp_async16(smem_u32(dEH + row * EST + col), gEH + row * CDIM + col);
            }
            cp_commit();
        }
        if (kt == 0) {
            if (tid < TN) esq_s[tid] = g_esq[nt * TN + tid];
            #pragma unroll
            for (int i = 0; i < 2; ++i) {
                #pragma unroll
                for (int j = 0; j < 4; ++j) {
                    #pragma unroll
                    for (int c2 = 0; c2 < 4; ++c2) acc[i][j][c2] = 0.0f;
                }
            }
        }

        // ---- compute chunk: 8 k16-steps; per ks: 4 ldsm.x4 + 8 HMMA ----
        const __half* bEH = EHs + (cc & 1) * (TN * EST);
        #pragma unroll
        for (int ks = 0; ks < 8; ++ks) {
            uint32_t ah[2][4];
            #pragma unroll
            for (int i = 0; i < 2; ++i) {
                int col = kt * KT + ks * 16 + a_colb;
                ldsm4(ah[i][0], ah[i][1], ah[i][2], ah[i][3],
                      smem_u32(QHs + (a_row + i * 16) * QST + col));
            }
            #pragma unroll
            for (int jj = 0; jj < 2; ++jj) {
                uint32_t bh[4];
                int ecol = ks * 16 + b_k;
                ldsm4(bh[0], bh[1], bh[2], bh[3],
                      smem_u32(bEH + (b_n + jj * 16) * EST + ecol));
                #pragma unroll
                for (int i = 0; i < 2; ++i) {
                    mma16816(acc[i][jj*2+0], ah[i][0],ah[i][1],ah[i][2],ah[i][3], bh[0],bh[1]);
                    mma16816(acc[i][jj*2+1], ah[i][0],ah[i][1],ah[i][2],ah[i][3], bh[2],bh[3]);
                }
            }
        }

        if (kt == 1) {
            // Epilogue: ascending n within lane; strict '<' = first index.
            // -2^-9 folds the 1/1024 (=16*64) de-scale with the -2 factor.
            #pragma unroll
            for (int j = 0; j < 4; ++j) {
                int nloc = wn * 32 + j * 8 + tl * 2;
                float2 es = *(const float2*)(esq_s + nloc);
                int n0 = nt * TN + nloc;
                #pragma unroll
                for (int i = 0; i < 2; ++i) {
                    #pragma unroll
                    for (int h = 0; h < 2; ++h) {
                        int r = i * 2 + h;
                        float t0 = __fadd_rn(qsq_r[r], es.x);
                        float d  = __fmaf_rn(-0.001953125f, acc[i][j][h*2+0], t0);
                        if (d < runMin[r]) {
                            runMin2[r] = runMin[r];
                            runMin[r] = d; runIdx[r] = n0;
                        } else if (d < runMin2[r]) runMin2[r] = d;
                        t0 = __fadd_rn(qsq_r[r], es.y);
                        d  = __fmaf_rn(-0.001953125f, acc[i][j][h*2+1], t0);
                        if (d < runMin[r]) {
                            runMin2[r] = runMin[r];
                            runMin[r] = d; runIdx[r] = n0 + 1;
                        } else if (d < runMin2[r]) runMin2[r] = d;
                    }
                }
            }
        }
    }

    // ---- Cross-lane top-2 reduction: [64 rows][16 slots] ----
    __syncthreads();   // all compute + async copies done; safe to overlay
    {
        const int slot = wn * 4 + tl;
        #pragma unroll
        for (int r = 0; r < 4; ++r) {
            int m = wm * 32 + (r >> 1) * 16 + gid + (r & 1) * 8;
            redMin [m * 16 + slot] = runMin[r];
            redIdx [m * 16 + slot] = runIdx[r];
            redMin2[m * 16 + slot] = runMin2[r];
        }
    }
    __syncthreads();

    float myDist = 0.0f;
    if (tid < TM) {
        float m1 = FLT_MAX, m2 = FLT_MAX; int i1 = 0;
        #pragma unroll
        for (int s2 = 0; s2 < 16; ++s2) {
            float v1 = redMin [tid * 16 + s2];
            int   id = redIdx [tid * 16 + s2];
            float v2 = redMin2[tid * 16 + s2];
            if (v1 < m1 || (v1 == m1 && id < i1)) {
                m2 = (m1 < m2) ? m1 : m2;
                m1 = v1; i1 = id;
            } else {
                m2 = (v1 < m2) ? v1 : m2;
            }
            m2 = (v2 < m2) ? v2 : m2;
        }
        int q = qbase + tid;
        g_key[q]  = ~0ull;
        g_prov[q] = i1;
        if (m2 - m1 <= DELTA) {
            int slot = atomicAdd(&g_nflag, 1);
            g_flist[slot] = q;
        }
        myDist = m1;
    }
    #pragma unroll
    for (int off = 16; off; off >>= 1)
        myDist += __shfl_down_sync(0xffffffffu, myDist, off);
    if (lane == 0 && warp < 2) atomicAdd(&g_dist_sum, myDist);
}

// ---------------------------------------------------------------------------
// Pass 2 (v3): exact rescore, E-stationary + query-parallel. (R11-verified.)
// ---------------------------------------------------------------------------
__global__ void __launch_bounds__(256)
vq_rescore_kernel(const float* __restrict__ Q, const float* __restrict__ E) {
    extern __shared__ float rsm[];
    float* Es    = rsm;                        // [RC][RES_ST] padded
    float* Qs    = rsm + RC * RES_ST;          // [QB][CDIM]
    float* qsq_s = Qs + QB * CDIM;             // [QB]
    float* esq_t = qsq_s + QB;                 // [RC]

    const int tid   = threadIdx.x;
    const int lane  = tid & 31;
    const int wq    = tid >> 5;                // warp -> query quad (0..7)
    const int nbase = blockIdx.x * RC;
    const int grp   = blockIdx.y;

    for (int idx = tid; idx < RC * (CDIM / 4); idx += 256) {
        int r = idx >> 6, k4 = idx & 63;
        float4 v = reinterpret_cast<const float4*>(
            E + (size_t)(nbase + r) * CDIM)[k4];
        *reinterpret_cast<float4*>(Es + r * RES_ST + k4 * 4) = v;
    }
    if (tid < RC) esq_t[tid] = g_esq[nbase + tid];

    const int nf = g_nflag;
    for (int f0 = grp * QB; f0 < nf; f0 += QG * QB) {
        __syncthreads();   // previous step done reading Qs
        for (int idx = tid; idx < QB * (CDIM / 4); idx += 256) {
            int r = idx >> 6, k4 = idx & 63;
            if (f0 + r < nf) {
                float4 v = reinterpret_cast<const float4*>(
                    Q + (size_t)g_flist[f0 + r] * CDIM)[k4];
                *reinterpret_cast<float4*>(Qs + r * CDIM + k4 * 4) = v;
            }
        }
        if (tid < QB && f0 + tid < nf) qsq_s[tid] = g_qsq[g_flist[f0 + tid]];
        __syncthreads();

        float acc[4][4];
        #pragma unroll
        for (int qi = 0; qi < 4; ++qi)
            #pragma unroll
            for (int ci = 0; ci < 4; ++ci) acc[qi][ci] = 0.0f;

        const float* qr = Qs + (wq * 4) * CDIM;
        const float* er = Es + lane * RES_ST;
        #pragma unroll 2
        for (int k4 = 0; k4 < 64; ++k4) {
            float4 e0 = *reinterpret_cast<const float4*>(er + 0 * 32 * RES_ST + k4 * 4);
            float4 e1 = *reinterpret_cast<const float4*>(er + 1 * 32 * RES_ST + k4 * 4);
            float4 e2 = *reinterpret_cast<const float4*>(er + 2 * 32 * RES_ST + k4 * 4);
            float4 e3 = *reinterpret_cast<const float4*>(er + 3 * 32 * RES_ST + k4 * 4);
            #pragma unroll
            for (int qi = 0; qi < 4; ++qi) {
                float4 qv = *reinterpret_cast<const float4*>(
                    qr + qi * CDIM + k4 * 4);
                acc[qi][0] = __fmaf_rn(qv.x, e0.x, acc[qi][0]);
                acc[qi][0] = __fmaf_rn(qv.y, e0.y, acc[qi][0]);
                acc[qi][0] = __fmaf_rn(qv.z, e0.z, acc[qi][0]);
                acc[qi][0] = __fmaf_rn(qv.w, e0.w, acc[qi][0]);
                acc[qi][1] = __fmaf_rn(qv.x, e1.x, acc[qi][1]);
                acc[qi][1] = __fmaf_rn(qv.y, e1.y, acc[qi][1]);
                acc[qi][1] = __fmaf_rn(qv.z, e1.z, acc[qi][1]);
                acc[qi][1] = __fmaf_rn(qv.w, e1.w, acc[qi][1]);
                acc[qi][2] = __fmaf_rn(qv.x, e2.x, acc[qi][2]);
                acc[qi][2] = __fmaf_rn(qv.y, e2.y, acc[qi][2]);
                acc[qi][2] = __fmaf_rn(qv.z, e2.z, acc[qi][2]);
                acc[qi][2] = __fmaf_rn(qv.w, e2.w, acc[qi][2]);
                acc[qi][3] = __fmaf_rn(qv.x, e3.x, acc[qi][3]);
                acc[qi][3] = __fmaf_rn(qv.y, e3.y, acc[qi][3]);
                acc[qi][3] = __fmaf_rn(qv.z, e3.z, acc[qi][3]);
                acc[qi][3] = __fmaf_rn(qv.w, e3.w, acc[qi][3]);
            }
        }

        #pragma unroll
        for (int qi = 0; qi < 4; ++qi) {
            int fq = f0 + wq * 4 + qi;         // warp-uniform
            if (fq >= nf) break;
            float qs = qsq_s[wq * 4 + qi];
            unsigned long long best = ~0ull;
            #pragma unroll
            for (int ci = 0; ci < 4; ++ci) {
                int n = nbase + lane + ci * 32;
                float t0 = __fadd_rn(qs, esq_t[lane + ci * 32]);
                float d  = __fmaf_rn(-2.0f, acc[qi][ci], t0);   // d > 0
                unsigned long long key =
                    ((unsigned long long)__float_as_uint(d) << 32) | (unsigned)n;
                best = (key < best) ? key : best;
            }
            #pragma unroll
            for (int off = 16; off; off >>= 1) {
                unsigned long long o =
                    __shfl_down_sync(0xffffffffu, best, off);
                best = (o < best) ? o : best;
            }
            if (lane == 0) atomicMin(&g_key[g_flist[fq]], best);
        }
    }
}

// ---------------------------------------------------------------------------
// Pass 3: finalize indices + gather quantized rows + loss scalar.
// ---------------------------------------------------------------------------
__global__ void __launch_bounds__(256)
vq_final3_kernel(const float* __restrict__ E, float* __restrict__ out,
                 float* __restrict__ out_loss) {
    if (blockIdx.x == 0 && threadIdx.x == 0)
        *out_loss = 1.25f * g_dist_sum * (1.0f / ((float)NQ * (float)CDIM));
    const int q    = blockIdx.x * 8 + (threadIdx.x >> 5);
    const int lane = threadIdx.x & 31;
    unsigned long long k = g_key[q];
    int idx = (k != ~0ull) ? (int)(k & 0xffffffffu) : g_prov[q];
    if (lane == 0) out[q] = (float)idx;
    const float4* src = reinterpret_cast<const float4*>(E + (size_t)idx * CDIM);
    float4* dst = reinterpret_cast<float4*>(out + NQ + (size_t)q * CDIM);
    dst[lane]      = src[lane];
    dst[lane + 32] = src[lane + 32];
}

extern "C" void kernel_launch(void* const* d_in, const int* in_sizes, int n_in,
                              void* d_out, int out_size) {
    const float* Q = (const float*)d_in[0];
    const float* E = (const float*)d_in[1];
    float* out = (float*)d_out;

    cudaFuncSetAttribute(vq_main_kernel,
                         cudaFuncAttributeMaxDynamicSharedMemorySize,
                         SMEM_TOTAL);
    cudaFuncSetAttribute(vq_rescore_kernel,
                         cudaFuncAttributeMaxDynamicSharedMemorySize,
                         RSMEM);

    vq_prep_kernel<<<(NC + NQ) / 8, 256>>>(Q, E);
    vq_main_kernel<<<NQ / TM, 256, SMEM_TOTAL>>>();
    vq_rescore_kernel<<<dim3(NC / RC, QG), 256, RSMEM>>>(Q, E);
    vq_final3_kernel<<<NQ / 8, 256>>>(E, out, out + out_size - 1);
}